// round 13
// baseline (speedup 1.0000x reference)
#include <cuda_runtime.h>
#include <cstdint>

#define BATCH 32
#define SEQ   512
#define DIMK  64
#define DPITCH 1024
#define BIGF  1e30f
#define L2E   1.4426950408889634f
#define LN2   0.6931471805599453f

// Diagonal-major distance scratch: Ddiag[b][p][i] = D[b, i, p-i]  (64 MB)
__device__ float g_Ddiag[BATCH * DPITCH * SEQ];

__device__ __forceinline__ float ex2f(float x) {
  float r; asm("ex2.approx.f32 %0, %1;" : "=f"(r) : "f"(x)); return r;
}
__device__ __forceinline__ float lg2f(float x) {
  float r; asm("lg2.approx.f32 %0, %1;" : "=f"(r) : "f"(x)); return r;
}
// softmin (base-2 domain): exact min/median/max; 2 EX2 + 1 LG2.
__device__ __forceinline__ float softmin3s(float a, float b, float c) {
  float u = fminf(a, b), v = fmaxf(a, b);
  float mn = fminf(u, c);
  float mx = fmaxf(v, c);
  float md = fmaxf(u, fminf(v, c));
  float s = 1.0f + ex2f(mn - md) + ex2f(mn - mx);
  return mn - lg2f(s);
}

// ---------------------------------------------------------------------------
// Phase 1: D = x2 + y2 - 2 x.y, diagonal-major output.
// R7/R12 GEMM verbatim (best measured, ~54us): 256 threads, 128x128 tile,
// halves split the 16 j-blocks (8 each), per-half 128x8 staging.
// ---------------------------------------------------------------------------
#define TI 128
#define TJ 128
#define YS_STRIDE 132
#define DST_STRIDE 9

__global__ __launch_bounds__(256) void gemm_diag_kernel(
    const float* __restrict__ X, const float* __restrict__ Y) {
  const int t    = threadIdx.x;
  const int half = t >> 7;
  const int tt   = t & 127;
  const int i0 = blockIdx.x * TI;
  const int j0 = blockIdx.y * TJ;
  const int b  = blockIdx.z;

  __shared__ float Ys[DIMK * YS_STRIDE];     // [k][j]
  __shared__ float y2s[TJ];
  __shared__ float Dst[2][TI * DST_STRIDE];  // per-half staging

  const float* Xb = X + ((size_t)b * SEQ + i0) * DIMK;
  const float* Yb = Y + ((size_t)b * SEQ + j0) * DIMK;

  for (int e = t; e < TJ * DIMK; e += 256) {
    int j = e >> 6;
    int k = e & 63;
    Ys[k * YS_STRIDE + j] = Yb[e];
  }

  float xr[DIMK];
  float x2 = 0.f;
#pragma unroll
  for (int k4 = 0; k4 < DIMK; k4 += 4) {
    float4 v = *reinterpret_cast<const float4*>(Xb + (size_t)tt * DIMK + k4);
    xr[k4] = v.x; xr[k4 + 1] = v.y; xr[k4 + 2] = v.z; xr[k4 + 3] = v.w;
  }
#pragma unroll
  for (int k = 0; k < DIMK; k++) x2 += xr[k] * xr[k];

  __syncthreads();

  if (half == 0) {
    float a = 0.f;
#pragma unroll
    for (int k = 0; k < DIMK; k++) {
      float yv = Ys[k * YS_STRIDE + tt];
      a += yv * yv;
    }
    y2s[tt] = a;
  }
  __syncthreads();

  float* gout = g_Ddiag + (size_t)b * (DPITCH * SEQ);
  const int w = tt >> 5, lane = tt & 31;

  for (int jj = 0; jj < 8; jj++) {
    const int jb = half * 8 + jj;
    float acc[8];
#pragma unroll
    for (int m = 0; m < 8; m++) acc[m] = 0.f;

#pragma unroll
    for (int k = 0; k < DIMK; k++) {
      const float4 ya = *reinterpret_cast<const float4*>(&Ys[k * YS_STRIDE + jb * 8]);
      const float4 yb = *reinterpret_cast<const float4*>(&Ys[k * YS_STRIDE + jb * 8 + 4]);
      const float xv = xr[k];
      acc[0] += xv * ya.x; acc[1] += xv * ya.y;
      acc[2] += xv * ya.z; acc[3] += xv * ya.w;
      acc[4] += xv * yb.x; acc[5] += xv * yb.y;
      acc[6] += xv * yb.z; acc[7] += xv * yb.w;
    }

#pragma unroll
    for (int m = 0; m < 8; m++) {
      Dst[half][tt * DST_STRIDE + m] = x2 + y2s[jb * 8 + m] - 2.f * acc[m];
    }
    __syncthreads();

    const int p0 = i0 + j0 + jb * 8;
    for (int dbase = w * 4; dbase < TI + 8 - 1; dbase += 16) {
      int d = dbase + (lane >> 3);
      int q = lane & 7;
      if (d < TI + 8 - 1) {
        int lo = d - 7 < 0 ? 0 : d - 7;
        int hi = d < TI - 1 ? d : TI - 1;
        int irow = lo + q;
        if (irow <= hi) {
          gout[(size_t)(p0 + d) * SEQ + (i0 + irow)] =
              Dst[half][irow * DST_STRIDE + (d - irow)];
        }
      }
    }
    __syncthreads();
  }
}

// ---------------------------------------------------------------------------
// Phase 2: wavefront DP — R2 step logic, TWO independent batches per CTA.
// 256 threads: warps 0-3 -> batch 2*cta, warps 4-7 -> batch 2*cta+1.
// Each SMSP hosts one warp from each half; the independent streams fill
// each other's MUFU/dependency bubbles. Joint __syncthreads (identical work
// per half -> no convoy). Per-half parity mailboxes. Base-2 scaled domain.
// ---------------------------------------------------------------------------
__global__ __launch_bounds__(256, 1) void softdtw_dp_kernel(float* __restrict__ out) {
  const int t = threadIdx.x;
  const int half = t >> 7;           // which batch within the CTA
  const int tt = t & 127;
  const int lane = tt & 31, w = tt >> 5;
  const int b = 2 * blockIdx.x + half;

  __shared__ float sb1[2][2][4];     // [half][parity][warp]
  __shared__ float sb2[2][2][4];
  if (t < 16) {
    (&sb1[0][0][0])[t] = BIGF;
    (&sb2[0][0][0])[t] = BIGF;
  }

  float v1[4], v2[4];
#pragma unroll
  for (int k = 0; k < 4; k++) { v1[k] = BIGF; v2[k] = BIGF; }

  const float* base = g_Ddiag + (size_t)b * (DPITCH * SEQ) + 4 * tt;
  __syncthreads();

#define DP_STEP(P, G4)                                                        \
  {                                                                           \
    const int rs = (P) & 1;                                                   \
    float nb1 = __shfl_up_sync(0xffffffffu, v1[3], 1);                        \
    float nb2 = __shfl_up_sync(0xffffffffu, v2[3], 1);                        \
    if (lane == 0) {                                                          \
      nb1 = (w == 0) ? BIGF : sb1[half][rs][w - 1];                           \
      nb2 = (w == 0) ? (((P) == 0) ? 0.0f : BIGF) : sb2[half][rs][w - 1];     \
    }                                                                         \
    float sm0 = softmin3s(nb2,   nb1,   v1[0]);                               \
    float sm1 = softmin3s(v2[0], v1[0], v1[1]);                               \
    float sm2 = softmin3s(v2[1], v1[1], v1[2]);                               \
    float sm3 = softmin3s(v2[2], v1[2], v1[3]);                               \
    unsigned pr = (unsigned)((P) - 4 * tt);                                   \
    float n0 = (pr      < (unsigned)SEQ) ? fmaf((G4).x, L2E, sm0) : BIGF;     \
    float n1 = (pr - 1u < (unsigned)SEQ) ? fmaf((G4).y, L2E, sm1) : BIGF;     \
    float n2 = (pr - 2u < (unsigned)SEQ) ? fmaf((G4).z, L2E, sm2) : BIGF;     \
    float n3 = (pr - 3u < (unsigned)SEQ) ? fmaf((G4).w, L2E, sm3) : BIGF;     \
    v2[0] = v1[0]; v2[1] = v1[1]; v2[2] = v1[2]; v2[3] = v1[3];               \
    v1[0] = n0;    v1[1] = n1;    v1[2] = n2;    v1[3] = n3;                  \
    if (lane == 31) {                                                         \
      sb1[half][rs ^ 1][w] = v1[3];                                           \
      sb2[half][rs ^ 1][w] = v2[3];                                           \
    }                                                                         \
    __syncthreads();                                                          \
  }

  // prefetch pipeline: groups of 8 diagonals
  float4 cur[8];
#pragma unroll
  for (int j = 0; j < 8; j++)
    cur[j] = *reinterpret_cast<const float4*>(base + (size_t)j * SEQ);

  for (int g = 0; g < 127; ++g) {
    float4 nxt[8];
#pragma unroll
    for (int j = 0; j < 8; j++)
      nxt[j] = *reinterpret_cast<const float4*>(base + (size_t)(8 * (g + 1) + j) * SEQ);
#pragma unroll
    for (int j = 0; j < 8; j++) {
      const int p = 8 * g + j;
      DP_STEP(p, cur[j]);
    }
#pragma unroll
    for (int j = 0; j < 8; j++) cur[j] = nxt[j];
  }
  // epilogue: p = 1016 .. 1022
#pragma unroll
  for (int j = 0; j < 7; j++) {
    const int p = 1016 + j;
    DP_STEP(p, cur[j]);
  }

  if (tt == 127) out[b] = v1[3] * LN2;  // R(511,511), back to nat domain
#undef DP_STEP
}

// ---------------------------------------------------------------------------
extern "C" void kernel_launch(void* const* d_in, const int* in_sizes, int n_in,
                              void* d_out, int out_size) {
  const float* X = (const float*)d_in[0];
  const float* Y = (const float*)d_in[1];
  float* out = (float*)d_out;

  dim3 grid_g(SEQ / TI, SEQ / TJ, BATCH);
  gemm_diag_kernel<<<grid_g, 256>>>(X, Y);
  softdtw_dp_kernel<<<BATCH / 2, 256>>>(out);
}

// round 14
// speedup vs baseline: 1.1336x; 1.1336x over previous
#include <cuda_runtime.h>
#include <cstdint>

#define BATCH 32
#define SEQ   512
#define DIMK  64
#define DPITCH 1024
#define BIGF  1e30f
#define L2E   1.4426950408889634f
#define LN2   0.6931471805599453f

// Diagonal-major distance scratch: Ddiag[b][p][i] = D[b, i, p-i]  (64 MB)
__device__ float g_Ddiag[BATCH * DPITCH * SEQ];

__device__ __forceinline__ float ex2f(float x) {
  float r; asm("ex2.approx.f32 %0, %1;" : "=f"(r) : "f"(x)); return r;
}
__device__ __forceinline__ float lg2f(float x) {
  float r; asm("lg2.approx.f32 %0, %1;" : "=f"(r) : "f"(x)); return r;
}
// softmin (base-2 domain): exact min/median/max; 2 EX2 + 1 LG2.
__device__ __forceinline__ float softmin3s(float a, float b, float c) {
  float u = fminf(a, b), v = fmaxf(a, b);
  float mn = fminf(u, c);
  float mx = fmaxf(v, c);
  float md = fmaxf(u, fminf(v, c));
  float s = 1.0f + ex2f(mn - md) + ex2f(mn - mx);
  return mn - lg2f(s);
}

// ---------------------------------------------------------------------------
// Phase 1: D = x2 + y2 - 2 x.y, diagonal-major output.
// v3: 256 threads, 128x128 tile, 2 rows x 8 cols per thread (X in smem too)
// -> smem bytes per FFMA x0.625 vs v2. Warp layout: 16 col-blocks x 2
// row-pairs => X broadcast, Y conflict-free. Output staged 32 rows x 128 cols
// per iteration via Dst stride 136 (135 % 32 = 7 -> diag reads conflict-free),
// stored as <=32-float coalesced diagonal runs.
// ---------------------------------------------------------------------------
#define XS_STRIDE 68
#define YS_STRIDE 132
#define DST_STRIDE 136

__global__ __launch_bounds__(256) void gemm_diag_kernel(
    const float* __restrict__ X, const float* __restrict__ Y) {
  __shared__ float Xs[128 * XS_STRIDE];   // [i][k]
  __shared__ float Ys[DIMK * YS_STRIDE];  // [k][j]
  __shared__ float y2s[128];
  __shared__ float x2s[128];
  __shared__ float Dst[32 * DST_STRIDE];  // one 32(i) x 128(j) chunk

  const int t = threadIdx.x;
  const int w = t >> 5, lane = t & 31;
  const int i0 = blockIdx.x << 7;
  const int j0 = blockIdx.y << 7;
  const int b  = blockIdx.z;

  const float* Xb = X + ((size_t)b * SEQ + i0) * DIMK;
  const float* Yb = Y + ((size_t)b * SEQ + j0) * DIMK;

  // X tile -> smem, coalesced float4 (2048 float4 over 256 threads)
  for (int e = t; e < 128 * 16; e += 256) {
    int row = e >> 4;
    int k4  = (e & 15) << 2;
    *reinterpret_cast<float4*>(&Xs[row * XS_STRIDE + k4]) =
        *reinterpret_cast<const float4*>(Xb + (size_t)row * DIMK + k4);
  }
  // Y tile transposed -> smem
  for (int e = t; e < 128 * DIMK; e += 256) {
    int j = e >> 6;
    int k = e & 63;
    Ys[k * YS_STRIDE + j] = Yb[e];
  }
  __syncthreads();

  if (t < 128) {
    float a = 0.f, c = 0.f;
#pragma unroll
    for (int k = 0; k < DIMK; k++) {
      float yv = Ys[k * YS_STRIDE + t];
      a += yv * yv;
      float xv = Xs[t * XS_STRIDE + k];
      c += xv * xv;
    }
    y2s[t] = a;
    x2s[t] = c;
  }
  __syncthreads();

  const int lrp = t >> 4;   // 0..15 -> local rows 2*lrp, 2*lrp+1
  const int cb  = t & 15;   // col block: cols cb*8 .. cb*8+7
  float* gout = g_Ddiag + (size_t)b * (DPITCH * SEQ);

  for (int it = 0; it < 4; it++) {
    const int r0 = it * 32 + 2 * lrp;
    const int r1 = r0 + 1;

    float acc0[8], acc1[8];
#pragma unroll
    for (int m = 0; m < 8; m++) { acc0[m] = 0.f; acc1[m] = 0.f; }

    for (int k4 = 0; k4 < DIMK; k4 += 4) {
      float4 xa = *reinterpret_cast<const float4*>(&Xs[r0 * XS_STRIDE + k4]);
      float4 xb = *reinterpret_cast<const float4*>(&Xs[r1 * XS_STRIDE + k4]);
      float xav[4] = {xa.x, xa.y, xa.z, xa.w};
      float xbv[4] = {xb.x, xb.y, xb.z, xb.w};
#pragma unroll
      for (int kk = 0; kk < 4; kk++) {
        const float* yrow = &Ys[(k4 + kk) * YS_STRIDE + cb * 8];
        float4 ya = *reinterpret_cast<const float4*>(yrow);
        float4 yb = *reinterpret_cast<const float4*>(yrow + 4);
        const float a0 = xav[kk], a1 = xbv[kk];
        acc0[0] += a0 * ya.x; acc0[1] += a0 * ya.y;
        acc0[2] += a0 * ya.z; acc0[3] += a0 * ya.w;
        acc0[4] += a0 * yb.x; acc0[5] += a0 * yb.y;
        acc0[6] += a0 * yb.z; acc0[7] += a0 * yb.w;
        acc1[0] += a1 * ya.x; acc1[1] += a1 * ya.y;
        acc1[2] += a1 * ya.z; acc1[3] += a1 * ya.w;
        acc1[4] += a1 * yb.x; acc1[5] += a1 * yb.y;
        acc1[6] += a1 * yb.z; acc1[7] += a1 * yb.w;
      }
    }

    const float x20 = x2s[r0], x21 = x2s[r1];
#pragma unroll
    for (int m = 0; m < 8; m++) {
      float y2 = y2s[cb * 8 + m];
      Dst[(2 * lrp)     * DST_STRIDE + cb * 8 + m] = fmaf(-2.f, acc0[m], x20 + y2);
      Dst[(2 * lrp + 1) * DST_STRIDE + cb * 8 + m] = fmaf(-2.f, acc1[m], x21 + y2);
    }
    __syncthreads();

    // diag-major store: chunk diag d = i_local + j in [0, 158], runs <= 32
    const int p0 = i0 + j0 + it * 32;
    const int ibase = i0 + it * 32;
    for (int d = w; d < 32 + 128 - 1; d += 8) {
      int lo = d - 127 > 0 ? d - 127 : 0;
      int hi = d < 31 ? d : 31;
      int i = lo + lane;
      if (i <= hi) {
        gout[(size_t)(p0 + d) * SEQ + (ibase + i)] =
            Dst[i * DST_STRIDE + (d - i)];
      }
    }
    __syncthreads();
  }
}

// ---------------------------------------------------------------------------
// Phase 2: wavefront DP — R2/R12 verbatim (reproduced 5x at ~136us, regs=93).
// 4 warps, 4 consecutive rows per thread; parity-double-buffered smem
// mailboxes; one barrier per step; 8-deep float4 register prefetch.
// Base-2 scaled domain (R' = R * log2e).
// ---------------------------------------------------------------------------
__global__ __launch_bounds__(128) void softdtw_dp_kernel(float* __restrict__ out) {
  const int b = blockIdx.x;
  const int t = threadIdx.x;
  const int lane = t & 31, w = t >> 5;

  __shared__ float sb1[2][4];
  __shared__ float sb2[2][4];
  if (t < 8) {
    (&sb1[0][0])[t] = BIGF;
    (&sb2[0][0])[t] = BIGF;
  }

  float v1[4], v2[4];
#pragma unroll
  for (int k = 0; k < 4; k++) { v1[k] = BIGF; v2[k] = BIGF; }

  const float* base = g_Ddiag + (size_t)b * (DPITCH * SEQ) + 4 * t;
  __syncthreads();

#define DP_STEP(P, G4)                                                        \
  {                                                                           \
    const int rs = (P) & 1;                                                   \
    float nb1 = __shfl_up_sync(0xffffffffu, v1[3], 1);                        \
    float nb2 = __shfl_up_sync(0xffffffffu, v2[3], 1);                        \
    if (lane == 0) {                                                          \
      nb1 = (w == 0) ? BIGF : sb1[rs][w - 1];                                 \
      nb2 = (w == 0) ? (((P) == 0) ? 0.0f : BIGF) : sb2[rs][w - 1];           \
    }                                                                         \
    float sm0 = softmin3s(nb2,   nb1,   v1[0]);                               \
    float sm1 = softmin3s(v2[0], v1[0], v1[1]);                               \
    float sm2 = softmin3s(v2[1], v1[1], v1[2]);                               \
    float sm3 = softmin3s(v2[2], v1[2], v1[3]);                               \
    unsigned pr = (unsigned)((P) - 4 * t);                                    \
    float n0 = (pr      < (unsigned)SEQ) ? fmaf((G4).x, L2E, sm0) : BIGF;     \
    float n1 = (pr - 1u < (unsigned)SEQ) ? fmaf((G4).y, L2E, sm1) : BIGF;     \
    float n2 = (pr - 2u < (unsigned)SEQ) ? fmaf((G4).z, L2E, sm2) : BIGF;     \
    float n3 = (pr - 3u < (unsigned)SEQ) ? fmaf((G4).w, L2E, sm3) : BIGF;     \
    v2[0] = v1[0]; v2[1] = v1[1]; v2[2] = v1[2]; v2[3] = v1[3];               \
    v1[0] = n0;    v1[1] = n1;    v1[2] = n2;    v1[3] = n3;                  \
    if (lane == 31) { sb1[rs ^ 1][w] = v1[3]; sb2[rs ^ 1][w] = v2[3]; }       \
    __syncthreads();                                                          \
  }

  // prefetch pipeline: groups of 8 diagonals
  float4 cur[8];
#pragma unroll
  for (int j = 0; j < 8; j++)
    cur[j] = *reinterpret_cast<const float4*>(base + (size_t)j * SEQ);

  for (int g = 0; g < 127; ++g) {
    float4 nxt[8];
#pragma unroll
    for (int j = 0; j < 8; j++)
      nxt[j] = *reinterpret_cast<const float4*>(base + (size_t)(8 * (g + 1) + j) * SEQ);
#pragma unroll
    for (int j = 0; j < 8; j++) {
      const int p = 8 * g + j;
      DP_STEP(p, cur[j]);
    }
#pragma unroll
    for (int j = 0; j < 8; j++) cur[j] = nxt[j];
  }
  // epilogue: p = 1016 .. 1022
#pragma unroll
  for (int j = 0; j < 7; j++) {
    const int p = 1016 + j;
    DP_STEP(p, cur[j]);
  }

  if (t == 127) out[b] = v1[3] * LN2;  // R(511,511), back to nat domain
#undef DP_STEP
}

// ---------------------------------------------------------------------------
extern "C" void kernel_launch(void* const* d_in, const int* in_sizes, int n_in,
                              void* d_out, int out_size) {
  const float* X = (const float*)d_in[0];
  const float* Y = (const float*)d_in[1];
  float* out = (float*)d_out;

  dim3 grid_g(4, 4, BATCH);     // 512 tiles of 128 x 128
  gemm_diag_kernel<<<grid_g, 256>>>(X, Y);
  softdtw_dp_kernel<<<BATCH, 128>>>(out);
}